// round 2
// baseline (speedup 1.0000x reference)
#include <cuda_runtime.h>
#include <cuda_bf16.h>
#include <math.h>

// Problem constants
#define B 4096
#define K 128
#define C 100
#define MARGIN 0.3f

// Scratch (device globals: no allocation allowed)
__device__ int   g_maxbits[B];   // per-row max of d^2 over same-label (float bits, >=0)
__device__ int   g_minbits[B];   // per-row min of d^2 over diff-label (float bits, >=0 or +inf)
__device__ float g_sq[B];        // squared norms
__device__ float g_ce[B];        // per-row cross-entropy
__device__ int   g_lab[B];       // labels as int32

// ---------------------------------------------------------------------------
// Kernel 1: squared norms + init of reduction buffers + label narrowing.
// One warp per row; lane loads one float4 (32 lanes * 4 = 128 floats).
// NOTE: labels arrive as int32 (JAX default x64-disabled downcasts int64).
// ---------------------------------------------------------------------------
__global__ void prep_kernel(const float* __restrict__ emb,
                            const int* __restrict__ labels) {
    int warp = (blockIdx.x * blockDim.x + threadIdx.x) >> 5;
    int lane = threadIdx.x & 31;
    if (warp >= B) return;
    float4 v = reinterpret_cast<const float4*>(emb)[warp * 32 + lane];
    float s = v.x * v.x + v.y * v.y + v.z * v.z + v.w * v.w;
    #pragma unroll
    for (int m = 16; m; m >>= 1) s += __shfl_xor_sync(0xffffffffu, s, m);
    if (lane == 0) {
        g_sq[warp]      = s;
        g_maxbits[warp] = 0;            // d^2 >= 0; diag guarantees max >= 0
        g_minbits[warp] = 0x7f800000;   // +inf
        g_lab[warp]     = labels[warp];
    }
}

// ---------------------------------------------------------------------------
// Kernel 2: tiled Gram matrix + fused hardest-positive/hardest-negative
// reduction on squared distances.
// Block: 16x16 threads, tile 128x128, micro-tile 8x8 per thread.
// Row mapping i = ty + 16*q, j = tx + 16*r  => smem reads with 129-float
// padded stride are bank-conflict-free.
// ---------------------------------------------------------------------------
#define PW_SMEM (2 * 128 * 129 * 4)

__global__ void __launch_bounds__(256, 1)
pairwise_kernel(const float* __restrict__ emb) {
    extern __shared__ float sm[];
    float* As = sm;                 // [128][129]
    float* Bs = sm + 128 * 129;     // [128][129]
    __shared__ int   labA[128], labB[128];
    __shared__ float sqA[128], sqB[128];

    const int tx  = threadIdx.x, ty = threadIdx.y;
    const int tid = ty * 16 + tx;
    const int i0  = blockIdx.y * 128;
    const int j0  = blockIdx.x * 128;

    // Load tiles (coalesced float4 global reads, conflict-free smem writes)
    const float4* e4 = reinterpret_cast<const float4*>(emb);
    #pragma unroll
    for (int f = tid; f < 128 * 32; f += 256) {
        int row = f >> 5, c4 = f & 31;
        float4 va = e4[(i0 + row) * 32 + c4];
        float4 vb = e4[(j0 + row) * 32 + c4];
        float* ap = &As[row * 129 + c4 * 4];
        ap[0] = va.x; ap[1] = va.y; ap[2] = va.z; ap[3] = va.w;
        float* bp = &Bs[row * 129 + c4 * 4];
        bp[0] = vb.x; bp[1] = vb.y; bp[2] = vb.z; bp[3] = vb.w;
    }
    if (tid < 128) {
        labA[tid] = g_lab[i0 + tid];
        labB[tid] = g_lab[j0 + tid];
        sqA[tid]  = g_sq[i0 + tid];
        sqB[tid]  = g_sq[j0 + tid];
    }
    __syncthreads();

    float acc[8][8];
    #pragma unroll
    for (int q = 0; q < 8; q++)
        #pragma unroll
        for (int r = 0; r < 8; r++) acc[q][r] = 0.0f;

    #pragma unroll 4
    for (int k = 0; k < K; k++) {
        float a[8], b[8];
        #pragma unroll
        for (int q = 0; q < 8; q++) a[q] = As[(ty + 16 * q) * 129 + k];
        #pragma unroll
        for (int r = 0; r < 8; r++) b[r] = Bs[(tx + 16 * r) * 129 + k];
        #pragma unroll
        for (int q = 0; q < 8; q++)
            #pragma unroll
            for (int r = 0; r < 8; r++)
                acc[q][r] = fmaf(a[q], b[r], acc[q][r]);
    }

    // Epilogue: d^2, masked max/min, reduce across tx (half-warp), atomic
    const float INF = __int_as_float(0x7f800000);
    #pragma unroll
    for (int q = 0; q < 8; q++) {
        int   i  = ty + 16 * q;
        int   li = labA[i];
        float si = sqA[i];
        float pos = 0.0f, neg = INF;
        #pragma unroll
        for (int r = 0; r < 8; r++) {
            int   j  = tx + 16 * r;
            float d2 = fmaxf(si + sqB[j] - 2.0f * acc[q][r], 0.0f);
            if (labB[j] == li) pos = fmaxf(pos, d2);
            else               neg = fminf(neg, d2);
        }
        #pragma unroll
        for (int m = 8; m; m >>= 1) {
            pos = fmaxf(pos, __shfl_xor_sync(0xffffffffu, pos, m));
            neg = fminf(neg, __shfl_xor_sync(0xffffffffu, neg, m));
        }
        if (tx == 0) {
            atomicMax(&g_maxbits[i0 + i], __float_as_int(pos));
            atomicMin(&g_minbits[i0 + i], __float_as_int(neg));
        }
    }
}

// ---------------------------------------------------------------------------
// Kernel 3: cross-entropy. 16 rows per block, W staged in smem (pad 132),
// each thread < 100 owns one class across all 16 rows.
// ---------------------------------------------------------------------------
#define CE_ROWS 16
#define CE_SMEM ((C * 132 + CE_ROWS * 129 + CE_ROWS * C) * 4)

__global__ void ce_kernel(const float* __restrict__ emb,
                          const float* __restrict__ w,
                          const float* __restrict__ bias) {
    extern __shared__ float sm[];
    float* w_s = sm;                       // [100][132]
    float* e_s = sm + C * 132;             // [16][129]
    float* lg  = e_s + CE_ROWS * 129;      // [16][100]

    int tid = threadIdx.x;                 // 128 threads
    int r0  = blockIdx.x * CE_ROWS;

    for (int f = tid; f < C * K; f += 128) {
        int c = f >> 7, k = f & 127;
        w_s[c * 132 + k] = w[f];
    }
    for (int f = tid; f < CE_ROWS * K; f += 128) {
        int r = f >> 7, k = f & 127;
        e_s[r * 129 + k] = emb[(r0 + r) * K + k];
    }
    __syncthreads();

    if (tid < C) {
        float accv[CE_ROWS];
        float bv = bias[tid];
        #pragma unroll
        for (int r = 0; r < CE_ROWS; r++) accv[r] = bv;
        for (int k = 0; k < K; k++) {
            float wv = w_s[tid * 132 + k];
            #pragma unroll
            for (int r = 0; r < CE_ROWS; r++)
                accv[r] = fmaf(wv, e_s[r * 129 + k], accv[r]);
        }
        #pragma unroll
        for (int r = 0; r < CE_ROWS; r++) lg[r * C + tid] = accv[r];
    }
    __syncthreads();

    if (tid < CE_ROWS) {
        int   lab = g_lab[r0 + tid];
        float m = -1e30f;
        for (int c = 0; c < C; c++) m = fmaxf(m, lg[tid * C + c]);
        float s = 0.0f;
        for (int c = 0; c < C; c++) s += expf(lg[tid * C + c] - m);
        g_ce[r0 + tid] = m + logf(s) - lg[tid * C + lab];
    }
}

// ---------------------------------------------------------------------------
// Kernel 4: final deterministic reduction -> scalar loss.
// ---------------------------------------------------------------------------
__global__ void finalize_kernel(float* __restrict__ out) {
    __shared__ float s1[1024], s2[1024];
    int t = threadIdx.x;
    float tr = 0.0f, ce = 0.0f;
    for (int i = t; i < B; i += 1024) {
        float mx = fmaxf(__int_as_float(g_maxbits[i]), 1e-12f);
        float mn = fmaxf(__int_as_float(g_minbits[i]), 1e-12f);
        float v  = sqrtf(mx) - sqrtf(mn) + MARGIN;   // -inf if no negatives
        tr += fmaxf(v, 0.0f);
        ce += g_ce[i];
    }
    s1[t] = tr; s2[t] = ce;
    __syncthreads();
    #pragma unroll
    for (int s = 512; s > 0; s >>= 1) {
        if (t < s) { s1[t] += s1[t + s]; s2[t] += s2[t + s]; }
        __syncthreads();
    }
    if (t == 0) out[0] = (s1[0] + s2[0]) * (1.0f / (float)B);
}

// ---------------------------------------------------------------------------
extern "C" void kernel_launch(void* const* d_in, const int* in_sizes, int n_in,
                              void* d_out, int out_size) {
    const float* emb    = (const float*)d_in[0];
    const int*   labels = (const int*)d_in[1];
    const float* fcw    = (const float*)d_in[2];
    const float* fcb    = (const float*)d_in[3];
    float*       out    = (float*)d_out;

    cudaFuncSetAttribute(pairwise_kernel,
                         cudaFuncAttributeMaxDynamicSharedMemorySize, PW_SMEM);
    cudaFuncSetAttribute(ce_kernel,
                         cudaFuncAttributeMaxDynamicSharedMemorySize, CE_SMEM);

    prep_kernel<<<(B * 32) / 256, 256>>>(emb, labels);
    pairwise_kernel<<<dim3(B / 128, B / 128), dim3(16, 16), PW_SMEM>>>(emb);
    ce_kernel<<<B / CE_ROWS, 128, CE_SMEM>>>(emb, fcw, fcb);
    finalize_kernel<<<1, 1024>>>(out);
}

// round 3
// speedup vs baseline: 1.2234x; 1.2234x over previous
#include <cuda_runtime.h>
#include <cuda_bf16.h>
#include <math.h>

// Problem constants
#define B 4096
#define K 128
#define C 100
#define MARGIN 0.3f

typedef unsigned long long u64;

// Scratch (device globals: no allocation allowed)
__device__ int   g_maxbits[B];   // per-row max of d^2 over same-label (float bits)
__device__ int   g_minbits[B];   // per-row min of d^2 over diff-label (float bits)
__device__ float g_sq[B];        // squared norms
__device__ float g_ce[B];        // per-row cross-entropy
__device__ int   g_lab[B];       // labels
__device__ float g_part_tr[16];  // partial triplet sums
__device__ float g_part_ce[16];  // partial ce sums

// ---------------------------------------------------------------------------
// Kernel 1: squared norms + init + labels (int32).
// ---------------------------------------------------------------------------
__global__ void prep_kernel(const float* __restrict__ emb,
                            const int* __restrict__ labels) {
    int warp = (blockIdx.x * blockDim.x + threadIdx.x) >> 5;
    int lane = threadIdx.x & 31;
    if (warp >= B) return;
    float4 v = reinterpret_cast<const float4*>(emb)[warp * 32 + lane];
    float s = v.x * v.x + v.y * v.y + v.z * v.z + v.w * v.w;
    #pragma unroll
    for (int m = 16; m; m >>= 1) s += __shfl_xor_sync(0xffffffffu, s, m);
    if (lane == 0) {
        g_sq[warp]      = s;
        g_maxbits[warp] = 0;
        g_minbits[warp] = 0x7f800000;   // +inf
        g_lab[warp]     = labels[warp];
    }
}

// ---------------------------------------------------------------------------
// Kernel 2: Gram tiles with packed fma.rn.f32x2 (2 FMA per issue slot).
// k processed in pairs; acc.lo accumulates even k, acc.hi odd k.
// Smem stride 130 floats (even -> 8B-aligned LDS.64; conflict-free reads).
// ---------------------------------------------------------------------------
#define PAD 130
#define PW_SMEM (2 * 128 * PAD * 4)

__global__ void __launch_bounds__(256, 1)
pairwise_kernel(const float* __restrict__ emb) {
    extern __shared__ float sm[];
    float* As = sm;                 // [128][130]
    float* Bs = sm + 128 * PAD;     // [128][130]
    __shared__ int   labA[128], labB[128];
    __shared__ float sqA[128], sqB[128];

    const int tx  = threadIdx.x, ty = threadIdx.y;
    const int tid = ty * 16 + tx;
    const int i0  = blockIdx.y * 128;
    const int j0  = blockIdx.x * 128;

    const float4* e4 = reinterpret_cast<const float4*>(emb);
    #pragma unroll
    for (int f = tid; f < 128 * 32; f += 256) {
        int row = f >> 5, c4 = f & 31;
        float4 va = e4[(i0 + row) * 32 + c4];
        float4 vb = e4[(j0 + row) * 32 + c4];
        float2* ap = reinterpret_cast<float2*>(&As[row * PAD + c4 * 4]);
        ap[0] = make_float2(va.x, va.y);
        ap[1] = make_float2(va.z, va.w);
        float2* bp = reinterpret_cast<float2*>(&Bs[row * PAD + c4 * 4]);
        bp[0] = make_float2(vb.x, vb.y);
        bp[1] = make_float2(vb.z, vb.w);
    }
    if (tid < 128) {
        labA[tid] = g_lab[i0 + tid];
        labB[tid] = g_lab[j0 + tid];
        sqA[tid]  = g_sq[i0 + tid];
        sqB[tid]  = g_sq[j0 + tid];
    }
    __syncthreads();

    u64 acc[8][8];
    #pragma unroll
    for (int q = 0; q < 8; q++)
        #pragma unroll
        for (int r = 0; r < 8; r++) acc[q][r] = 0ull;

    #pragma unroll 4
    for (int kp = 0; kp < K / 2; kp++) {
        u64 a2[8], b2[8];
        #pragma unroll
        for (int q = 0; q < 8; q++)
            a2[q] = *reinterpret_cast<const u64*>(&As[(ty + 16 * q) * PAD + 2 * kp]);
        #pragma unroll
        for (int r = 0; r < 8; r++)
            b2[r] = *reinterpret_cast<const u64*>(&Bs[(tx + 16 * r) * PAD + 2 * kp]);
        #pragma unroll
        for (int q = 0; q < 8; q++)
            #pragma unroll
            for (int r = 0; r < 8; r++)
                asm("fma.rn.f32x2 %0, %1, %2, %0;"
                    : "+l"(acc[q][r]) : "l"(a2[q]), "l"(b2[r]));
    }

    // Epilogue: combine packed lanes, d^2, masked max/min, half-warp reduce
    const float INF = __int_as_float(0x7f800000);
    #pragma unroll
    for (int q = 0; q < 8; q++) {
        int   i  = ty + 16 * q;
        int   li = labA[i];
        float si = sqA[i];
        float pos = 0.0f, neg = INF;
        #pragma unroll
        for (int r = 0; r < 8; r++) {
            int   j  = tx + 16 * r;
            float glo = __uint_as_float((unsigned)(acc[q][r] & 0xffffffffull));
            float ghi = __uint_as_float((unsigned)(acc[q][r] >> 32));
            float g   = glo + ghi;
            float d2  = fmaxf(si + sqB[j] - 2.0f * g, 0.0f);
            if (labB[j] == li) pos = fmaxf(pos, d2);
            else               neg = fminf(neg, d2);
        }
        #pragma unroll
        for (int m = 8; m; m >>= 1) {
            pos = fmaxf(pos, __shfl_xor_sync(0xffffffffu, pos, m));
            neg = fminf(neg, __shfl_xor_sync(0xffffffffu, neg, m));
        }
        if (tx == 0) {
            atomicMax(&g_maxbits[i0 + i], __float_as_int(pos));
            atomicMin(&g_minbits[i0 + i], __float_as_int(neg));
        }
    }
}

// ---------------------------------------------------------------------------
// Kernel 3: cross-entropy. 16 rows/block, W staged in smem.
// ---------------------------------------------------------------------------
#define CE_ROWS 16
#define CE_SMEM ((C * 132 + CE_ROWS * 129 + CE_ROWS * C) * 4)

__global__ void ce_kernel(const float* __restrict__ emb,
                          const float* __restrict__ w,
                          const float* __restrict__ bias) {
    extern __shared__ float sm[];
    float* w_s = sm;                       // [100][132]
    float* e_s = sm + C * 132;             // [16][129]
    float* lg  = e_s + CE_ROWS * 129;      // [16][100]

    int tid = threadIdx.x;                 // 128 threads
    int r0  = blockIdx.x * CE_ROWS;

    for (int f = tid; f < C * K; f += 128) {
        int c = f >> 7, k = f & 127;
        w_s[c * 132 + k] = w[f];
    }
    for (int f = tid; f < CE_ROWS * K; f += 128) {
        int r = f >> 7, k = f & 127;
        e_s[r * 129 + k] = emb[(r0 + r) * K + k];
    }
    __syncthreads();

    if (tid < C) {
        float accv[CE_ROWS];
        float bv = bias[tid];
        #pragma unroll
        for (int r = 0; r < CE_ROWS; r++) accv[r] = bv;
        for (int k = 0; k < K; k++) {
            float wv = w_s[tid * 132 + k];
            #pragma unroll
            for (int r = 0; r < CE_ROWS; r++)
                accv[r] = fmaf(wv, e_s[r * 129 + k], accv[r]);
        }
        #pragma unroll
        for (int r = 0; r < CE_ROWS; r++) lg[r * C + tid] = accv[r];
    }
    __syncthreads();

    if (tid < CE_ROWS) {
        int   lab = g_lab[r0 + tid];
        float m = -1e30f;
        for (int c = 0; c < C; c++) m = fmaxf(m, lg[tid * C + c]);
        float s = 0.0f;
        for (int c = 0; c < C; c++) s += expf(lg[tid * C + c] - m);
        g_ce[r0 + tid] = m + logf(s) - lg[tid * C + lab];
    }
}

// ---------------------------------------------------------------------------
// Kernel 4a: 16-block deterministic partial reduction.
// ---------------------------------------------------------------------------
__global__ void reduce1_kernel() {
    __shared__ float s1[256], s2[256];
    int t = threadIdx.x;
    int i = blockIdx.x * 256 + t;
    float mx = fmaxf(__int_as_float(g_maxbits[i]), 1e-12f);
    float mn = fmaxf(__int_as_float(g_minbits[i]), 1e-12f);
    float tr = fmaxf(sqrtf(mx) - sqrtf(mn) + MARGIN, 0.0f);
    s1[t] = tr; s2[t] = g_ce[i];
    __syncthreads();
    #pragma unroll
    for (int s = 128; s > 0; s >>= 1) {
        if (t < s) { s1[t] += s1[t + s]; s2[t] += s2[t + s]; }
        __syncthreads();
    }
    if (t == 0) { g_part_tr[blockIdx.x] = s1[0]; g_part_ce[blockIdx.x] = s2[0]; }
}

// Kernel 4b: final scalar (deterministic serial sum of 16 partials).
__global__ void reduce2_kernel(float* __restrict__ out) {
    if (threadIdx.x == 0) {
        float s = 0.0f;
        #pragma unroll
        for (int i = 0; i < 16; i++) s += g_part_tr[i] + g_part_ce[i];
        out[0] = s * (1.0f / (float)B);
    }
}

// ---------------------------------------------------------------------------
extern "C" void kernel_launch(void* const* d_in, const int* in_sizes, int n_in,
                              void* d_out, int out_size) {
    const float* emb    = (const float*)d_in[0];
    const int*   labels = (const int*)d_in[1];
    const float* fcw    = (const float*)d_in[2];
    const float* fcb    = (const float*)d_in[3];
    float*       out    = (float*)d_out;

    cudaFuncSetAttribute(pairwise_kernel,
                         cudaFuncAttributeMaxDynamicSharedMemorySize, PW_SMEM);
    cudaFuncSetAttribute(ce_kernel,
                         cudaFuncAttributeMaxDynamicSharedMemorySize, CE_SMEM);

    prep_kernel<<<(B * 32) / 256, 256>>>(emb, labels);
    pairwise_kernel<<<dim3(B / 128, B / 128), dim3(16, 16), PW_SMEM>>>(emb);
    ce_kernel<<<B / CE_ROWS, 128, CE_SMEM>>>(emb, fcw, fcb);
    reduce1_kernel<<<16, 256>>>();
    reduce2_kernel<<<1, 32>>>(out);
}

// round 5
// speedup vs baseline: 1.8160x; 1.4843x over previous
#include <cuda_runtime.h>
#include <cuda_bf16.h>
#include <math.h>

// Problem constants
#define B 4096
#define K 128
#define C 100
#define MARGIN 0.3f

typedef unsigned long long u64;

// Scratch (device globals)
__device__ int   g_maxbits[B];   // per-row max d^2 over same-label (float bits)
__device__ int   g_minbits[B];   // per-row min d^2 over diff-label (float bits)
__device__ float g_sq[B];
__device__ float g_ce[B];
__device__ int   g_lab[B];
__device__ float g_part_tr[16];
__device__ float g_part_ce[16];

// ---------------------------------------------------------------------------
// Kernel 1: squared norms + init + labels (int32).
// ---------------------------------------------------------------------------
__global__ void prep_kernel(const float* __restrict__ emb,
                            const int* __restrict__ labels) {
    int warp = (blockIdx.x * blockDim.x + threadIdx.x) >> 5;
    int lane = threadIdx.x & 31;
    if (warp >= B) return;
    float4 v = reinterpret_cast<const float4*>(emb)[warp * 32 + lane];
    float s = v.x * v.x + v.y * v.y + v.z * v.z + v.w * v.w;
    #pragma unroll
    for (int m = 16; m; m >>= 1) s += __shfl_xor_sync(0xffffffffu, s, m);
    if (lane == 0) {
        g_sq[warp]      = s;
        g_maxbits[warp] = 0;            // diag d^2=0, same label -> max >= 0
        g_minbits[warp] = 0x7f800000;   // +inf
        g_lab[warp]     = labels[warp];
    }
}

// ---------------------------------------------------------------------------
// Kernel 2: upper-triangular Gram tiles with packed fma.rn.f32x2.
// Grid: 528 blocks = 32*33/2 block-pairs (by <= bx). Off-diagonal blocks
// update BOTH row-side (i over j) and col-side (j over i) reductions, so
// GEMM work is halved vs the full 1024-block grid.
// Block 16x16 threads, 128x128 tile, 8x8 micro-tile, k in pairs (f32x2).
// ---------------------------------------------------------------------------
#define PAD 130
#define PW_SMEM (2 * 128 * PAD * 4)

__global__ void __launch_bounds__(256, 1)
pairwise_kernel(const float* __restrict__ emb) {
    extern __shared__ float sm[];
    float* As = sm;                 // [128][130]
    float* Bs = sm + 128 * PAD;     // [128][130]
    __shared__ int   labA[128], labB[128];
    __shared__ float sqA[128], sqB[128];
    __shared__ float s_cp[8][128], s_cn[8][128];   // col-side warp partials

    // Triangular block decode: by <= bx
    int bid = blockIdx.x;
    float tf = sqrtf(8.0f * (float)bid + 1.0f);
    int bx = (int)((tf - 1.0f) * 0.5f);
    while ((bx + 1) * (bx + 2) / 2 <= bid) bx++;
    while (bx * (bx + 1) / 2 > bid) bx--;
    int by = bid - bx * (bx + 1) / 2;
    const bool diag = (by == bx);

    const int tx  = threadIdx.x, ty = threadIdx.y;
    const int tid = ty * 16 + tx;
    const int wid = tid >> 5;
    const int i0  = by * 128;
    const int j0  = bx * 128;

    const float4* e4 = reinterpret_cast<const float4*>(emb);
    #pragma unroll
    for (int f = tid; f < 128 * 32; f += 256) {
        int row = f >> 5, c4 = f & 31;
        float4 va = e4[(i0 + row) * 32 + c4];
        float4 vb = e4[(j0 + row) * 32 + c4];
        float2* ap = reinterpret_cast<float2*>(&As[row * PAD + c4 * 4]);
        ap[0] = make_float2(va.x, va.y);
        ap[1] = make_float2(va.z, va.w);
        float2* bp = reinterpret_cast<float2*>(&Bs[row * PAD + c4 * 4]);
        bp[0] = make_float2(vb.x, vb.y);
        bp[1] = make_float2(vb.z, vb.w);
    }
    if (tid < 128) {
        labA[tid] = g_lab[i0 + tid];
        labB[tid] = g_lab[j0 + tid];
        sqA[tid]  = g_sq[i0 + tid];
        sqB[tid]  = g_sq[j0 + tid];
    }
    __syncthreads();

    u64 acc[8][8];
    #pragma unroll
    for (int q = 0; q < 8; q++)
        #pragma unroll
        for (int r = 0; r < 8; r++) acc[q][r] = 0ull;

    #pragma unroll 2
    for (int kp = 0; kp < K / 2; kp++) {
        u64 a2[8], b2[8];
        #pragma unroll
        for (int q = 0; q < 8; q++)
            a2[q] = *reinterpret_cast<const u64*>(&As[(ty + 16 * q) * PAD + 2 * kp]);
        #pragma unroll
        for (int r = 0; r < 8; r++)
            b2[r] = *reinterpret_cast<const u64*>(&Bs[(tx + 16 * r) * PAD + 2 * kp]);
        #pragma unroll
        for (int q = 0; q < 8; q++)
            #pragma unroll
            for (int r = 0; r < 8; r++)
                asm("fma.rn.f32x2 %0, %1, %2, %0;"
                    : "+l"(acc[q][r]) : "l"(a2[q]), "l"(b2[r]));
    }

    // Epilogue: row-side AND col-side masked reductions on d^2.
    const float INF = __int_as_float(0x7f800000);
    float colPos[8], colNeg[8];
    #pragma unroll
    for (int r = 0; r < 8; r++) { colPos[r] = 0.0f; colNeg[r] = INF; }

    #pragma unroll
    for (int q = 0; q < 8; q++) {
        int   i  = ty + 16 * q;
        int   li = labA[i];
        float si = sqA[i];
        float pos = 0.0f, neg = INF;
        #pragma unroll
        for (int r = 0; r < 8; r++) {
            int   j   = tx + 16 * r;
            float glo = __uint_as_float((unsigned)(acc[q][r] & 0xffffffffull));
            float ghi = __uint_as_float((unsigned)(acc[q][r] >> 32));
            float d2  = fmaxf(si + sqB[j] - 2.0f * (glo + ghi), 0.0f);
            bool same = (labB[j] == li);
            if (same) { pos = fmaxf(pos, d2); colPos[r] = fmaxf(colPos[r], d2); }
            else      { neg = fminf(neg, d2); colNeg[r] = fminf(colNeg[r], d2); }
        }
        #pragma unroll
        for (int m = 8; m; m >>= 1) {
            pos = fmaxf(pos, __shfl_xor_sync(0xffffffffu, pos, m));
            neg = fminf(neg, __shfl_xor_sync(0xffffffffu, neg, m));
        }
        if (tx == 0) {
            atomicMax(&g_maxbits[i0 + i], __float_as_int(pos));
            atomicMin(&g_minbits[i0 + i], __float_as_int(neg));
        }
    }

    // Col-side (only useful off-diagonal): combine the two ty's per warp,
    // stage warp partials, then 128-thread final combine + global atomics.
    if (!diag) {
        #pragma unroll
        for (int r = 0; r < 8; r++) {
            float p = fmaxf(colPos[r], __shfl_xor_sync(0xffffffffu, colPos[r], 16));
            float n = fminf(colNeg[r], __shfl_xor_sync(0xffffffffu, colNeg[r], 16));
            if ((tid & 16) == 0) {          // one ty of the pair writes
                s_cp[wid][r * 16 + tx] = p;
                s_cn[wid][r * 16 + tx] = n;
            }
        }
        __syncthreads();
        if (tid < 128) {
            float p = s_cp[0][tid], n = s_cn[0][tid];
            #pragma unroll
            for (int w = 1; w < 8; w++) {
                p = fmaxf(p, s_cp[w][tid]);
                n = fminf(n, s_cn[w][tid]);
            }
            atomicMax(&g_maxbits[j0 + tid], __float_as_int(p));
            atomicMin(&g_minbits[j0 + tid], __float_as_int(n));
        }
    }
}

// ---------------------------------------------------------------------------
// Kernel 3: cross-entropy. 16 rows/block, W staged in smem.
// ---------------------------------------------------------------------------
#define CE_ROWS 16
#define CE_SMEM ((C * 132 + CE_ROWS * 129 + CE_ROWS * C) * 4)

__global__ void ce_kernel(const float* __restrict__ emb,
                          const float* __restrict__ w,
                          const float* __restrict__ bias) {
    extern __shared__ float smf[];
    float* w_s = smf;                      // [100][132]
    float* e_s = smf + C * 132;            // [16][129]
    float* lg  = e_s + CE_ROWS * 129;      // [16][100]

    int tid = threadIdx.x;                 // 128 threads
    int r0  = blockIdx.x * CE_ROWS;

    for (int f = tid; f < C * K; f += 128) {
        int c = f >> 7, k = f & 127;
        w_s[c * 132 + k] = w[f];
    }
    for (int f = tid; f < CE_ROWS * K; f += 128) {
        int r = f >> 7, k = f & 127;
        e_s[r * 129 + k] = emb[(r0 + r) * K + k];
    }
    __syncthreads();

    if (tid < C) {
        float accv[CE_ROWS];
        float bv = bias[tid];
        #pragma unroll
        for (int r = 0; r < CE_ROWS; r++) accv[r] = bv;
        for (int k = 0; k < K; k++) {
            float wv = w_s[tid * 132 + k];
            #pragma unroll
            for (int r = 0; r < CE_ROWS; r++)
                accv[r] = fmaf(wv, e_s[r * 129 + k], accv[r]);
        }
        #pragma unroll
        for (int r = 0; r < CE_ROWS; r++) lg[r * C + tid] = accv[r];
    }
    __syncthreads();

    if (tid < CE_ROWS) {
        int   lab = g_lab[r0 + tid];
        float m = -1e30f;
        for (int c = 0; c < C; c++) m = fmaxf(m, lg[tid * C + c]);
        float s = 0.0f;
        for (int c = 0; c < C; c++) s += expf(lg[tid * C + c] - m);
        g_ce[r0 + tid] = m + logf(s) - lg[tid * C + lab];
    }
}

// ---------------------------------------------------------------------------
// Kernel 4a/4b: deterministic final reduction.
// ---------------------------------------------------------------------------
__global__ void reduce1_kernel() {
    __shared__ float s1[256], s2[256];
    int t = threadIdx.x;
    int i = blockIdx.x * 256 + t;
    float mx = fmaxf(__int_as_float(g_maxbits[i]), 1e-12f);
    float mn = fmaxf(__int_as_float(g_minbits[i]), 1e-12f);
    float tr = fmaxf(sqrtf(mx) - sqrtf(mn) + MARGIN, 0.0f);
    s1[t] = tr; s2[t] = g_ce[i];
    __syncthreads();
    #pragma unroll
    for (int s = 128; s > 0; s >>= 1) {
        if (t < s) { s1[t] += s1[t + s]; s2[t] += s2[t + s]; }
        __syncthreads();
    }
    if (t == 0) { g_part_tr[blockIdx.x] = s1[0]; g_part_ce[blockIdx.x] = s2[0]; }
}

__global__ void reduce2_kernel(float* __restrict__ out) {
    if (threadIdx.x == 0) {
        float s = 0.0f;
        #pragma unroll
        for (int i = 0; i < 16; i++) s += g_part_tr[i] + g_part_ce[i];
        out[0] = s * (1.0f / (float)B);
    }
}

// ---------------------------------------------------------------------------
extern "C" void kernel_launch(void* const* d_in, const int* in_sizes, int n_in,
                              void* d_out, int out_size) {
    const float* emb    = (const float*)d_in[0];
    const int*   labels = (const int*)d_in[1];
    const float* fcw    = (const float*)d_in[2];
    const float* fcb    = (const float*)d_in[3];
    float*       out    = (float*)d_out;

    cudaFuncSetAttribute(pairwise_kernel,
                         cudaFuncAttributeMaxDynamicSharedMemorySize, PW_SMEM);
    cudaFuncSetAttribute(ce_kernel,
                         cudaFuncAttributeMaxDynamicSharedMemorySize, CE_SMEM);

    prep_kernel<<<(B * 32) / 256, 256>>>(emb, labels);
    pairwise_kernel<<<(32 * 33) / 2, dim3(16, 16), PW_SMEM>>>(emb);
    ce_kernel<<<B / CE_ROWS, 128, CE_SMEM>>>(emb, fcw, fcb);
    reduce1_kernel<<<16, 256>>>();
    reduce2_kernel<<<1, 32>>>(out);
}

// round 6
// speedup vs baseline: 2.0949x; 1.1536x over previous
#include <cuda_runtime.h>
#include <cuda_bf16.h>
#include <math.h>

// Problem constants
#define B 4096
#define K 128
#define C 100
#define MARGIN 0.3f

#define PW_BLOCKS ((32 * 33) / 2)   // 528 triangular 128x128 tiles
#define CE_ROWS 16
#define CE_BLOCKS (B / CE_ROWS)     // 256

typedef unsigned long long u64;

// Scratch (device globals)
__device__ int   g_maxbits[B];
__device__ int   g_minbits[B];
__device__ float g_sq[B];
__device__ float g_ce[B];
__device__ int   g_lab[B];
__device__ float g_part_tr[32];
__device__ float g_part_ce[32];

// ---------------------------------------------------------------------------
// Kernel 1: squared norms + init + labels (int32).
// ---------------------------------------------------------------------------
__global__ void prep_kernel(const float* __restrict__ emb,
                            const int* __restrict__ labels) {
    int warp = (blockIdx.x * blockDim.x + threadIdx.x) >> 5;
    int lane = threadIdx.x & 31;
    if (warp >= B) return;
    float4 v = reinterpret_cast<const float4*>(emb)[warp * 32 + lane];
    float s = v.x * v.x + v.y * v.y + v.z * v.z + v.w * v.w;
    #pragma unroll
    for (int m = 16; m; m >>= 1) s += __shfl_xor_sync(0xffffffffu, s, m);
    if (lane == 0) {
        g_sq[warp]      = s;
        g_maxbits[warp] = 0;
        g_minbits[warp] = 0x7f800000;   // +inf
        g_lab[warp]     = labels[warp];
    }
}

// ---------------------------------------------------------------------------
// Fused kernel: blocks [0,528) = triangular Gram+triplet tiles;
// blocks [528,784) = cross-entropy (16 rows each). CE blocks are short and
// pack into the ragged final wave of the pairwise grid.
// ---------------------------------------------------------------------------
#define PAD 130
#define PW_SMEM (2 * 128 * PAD * 4)

__device__ __forceinline__ void pairwise_body(float* sm, const float* __restrict__ emb,
                                              int bid) {
    float* As = sm;                 // [128][130]
    float* Bs = sm + 128 * PAD;     // [128][130]
    __shared__ int   labA[128], labB[128];
    __shared__ float sqA[128], sqB[128];
    __shared__ float s_cp[8][128], s_cn[8][128];

    // Triangular block decode: by <= bx
    float tf = sqrtf(8.0f * (float)bid + 1.0f);
    int bx = (int)((tf - 1.0f) * 0.5f);
    while ((bx + 1) * (bx + 2) / 2 <= bid) bx++;
    while (bx * (bx + 1) / 2 > bid) bx--;
    int by = bid - bx * (bx + 1) / 2;
    const bool diag = (by == bx);

    const int tx  = threadIdx.x & 15, ty = threadIdx.x >> 4;
    const int tid = threadIdx.x;
    const int wid = tid >> 5;
    const int i0  = by * 128;
    const int j0  = bx * 128;

    const float4* e4 = reinterpret_cast<const float4*>(emb);
    #pragma unroll
    for (int f = tid; f < 128 * 32; f += 256) {
        int row = f >> 5, c4 = f & 31;
        float4 va = e4[(i0 + row) * 32 + c4];
        float4 vb = e4[(j0 + row) * 32 + c4];
        float2* ap = reinterpret_cast<float2*>(&As[row * PAD + c4 * 4]);
        ap[0] = make_float2(va.x, va.y);
        ap[1] = make_float2(va.z, va.w);
        float2* bp = reinterpret_cast<float2*>(&Bs[row * PAD + c4 * 4]);
        bp[0] = make_float2(vb.x, vb.y);
        bp[1] = make_float2(vb.z, vb.w);
    }
    if (tid < 128) {
        labA[tid] = g_lab[i0 + tid];
        labB[tid] = g_lab[j0 + tid];
        sqA[tid]  = g_sq[i0 + tid];
        sqB[tid]  = g_sq[j0 + tid];
    }
    __syncthreads();

    u64 acc[8][8];
    #pragma unroll
    for (int q = 0; q < 8; q++)
        #pragma unroll
        for (int r = 0; r < 8; r++) acc[q][r] = 0ull;

    #pragma unroll 2
    for (int kp = 0; kp < K / 2; kp++) {
        u64 a2[8], b2[8];
        #pragma unroll
        for (int q = 0; q < 8; q++)
            a2[q] = *reinterpret_cast<const u64*>(&As[(ty + 16 * q) * PAD + 2 * kp]);
        #pragma unroll
        for (int r = 0; r < 8; r++)
            b2[r] = *reinterpret_cast<const u64*>(&Bs[(tx + 16 * r) * PAD + 2 * kp]);
        #pragma unroll
        for (int q = 0; q < 8; q++)
            #pragma unroll
            for (int r = 0; r < 8; r++)
                asm("fma.rn.f32x2 %0, %1, %2, %0;"
                    : "+l"(acc[q][r]) : "l"(a2[q]), "l"(b2[r]));
    }

    const float INF = __int_as_float(0x7f800000);
    float colPos[8], colNeg[8];
    #pragma unroll
    for (int r = 0; r < 8; r++) { colPos[r] = 0.0f; colNeg[r] = INF; }

    #pragma unroll
    for (int q = 0; q < 8; q++) {
        int   i  = ty + 16 * q;
        int   li = labA[i];
        float si = sqA[i];
        float pos = 0.0f, neg = INF;
        #pragma unroll
        for (int r = 0; r < 8; r++) {
            int   j   = tx + 16 * r;
            float glo = __uint_as_float((unsigned)(acc[q][r] & 0xffffffffull));
            float ghi = __uint_as_float((unsigned)(acc[q][r] >> 32));
            float d2  = fmaxf(si + sqB[j] - 2.0f * (glo + ghi), 0.0f);
            bool same = (labB[j] == li);
            if (same) { pos = fmaxf(pos, d2); colPos[r] = fmaxf(colPos[r], d2); }
            else      { neg = fminf(neg, d2); colNeg[r] = fminf(colNeg[r], d2); }
        }
        #pragma unroll
        for (int m = 8; m; m >>= 1) {
            pos = fmaxf(pos, __shfl_xor_sync(0xffffffffu, pos, m));
            neg = fminf(neg, __shfl_xor_sync(0xffffffffu, neg, m));
        }
        if (tx == 0) {
            atomicMax(&g_maxbits[i0 + i], __float_as_int(pos));
            atomicMin(&g_minbits[i0 + i], __float_as_int(neg));
        }
    }

    if (!diag) {
        #pragma unroll
        for (int r = 0; r < 8; r++) {
            float p = fmaxf(colPos[r], __shfl_xor_sync(0xffffffffu, colPos[r], 16));
            float n = fminf(colNeg[r], __shfl_xor_sync(0xffffffffu, colNeg[r], 16));
            if ((tid & 16) == 0) {
                s_cp[wid][r * 16 + tx] = p;
                s_cn[wid][r * 16 + tx] = n;
            }
        }
        __syncthreads();
        if (tid < 128) {
            float p = s_cp[0][tid], n = s_cn[0][tid];
            #pragma unroll
            for (int w = 1; w < 8; w++) {
                p = fmaxf(p, s_cp[w][tid]);
                n = fminf(n, s_cn[w][tid]);
            }
            atomicMax(&g_maxbits[j0 + tid], __float_as_int(p));
            atomicMin(&g_minbits[j0 + tid], __float_as_int(n));
        }
    }
}

// CE body: 256 threads. Two class-groups (threads 0-99 rows 0-7,
// threads 128-227 rows 8-15). w_s stride 133 => conflict-free (gcd(5,32)=1).
__device__ __forceinline__ void ce_body(float* sm, const float* __restrict__ emb,
                                        const float* __restrict__ w,
                                        const float* __restrict__ bias, int bid) {
    float* w_s = sm;                        // [100][133]
    float* e_s = sm + C * 133;              // [16][129]
    float* lg  = e_s + CE_ROWS * 129;       // [16][100]

    int tid = threadIdx.x;                  // 256 threads
    int r0  = bid * CE_ROWS;

    for (int f = tid; f < C * K; f += 256) {
        int c = f >> 7, k = f & 127;
        w_s[c * 133 + k] = w[f];
    }
    for (int f = tid; f < CE_ROWS * K; f += 256) {
        int r = f >> 7, k = f & 127;
        e_s[r * 129 + k] = emb[(r0 + r) * K + k];
    }
    __syncthreads();

    int grp = tid >> 7;          // 0 or 1
    int c   = tid & 127;
    if (c < C) {
        float accv[8];
        float bv = bias[c];
        #pragma unroll
        for (int r = 0; r < 8; r++) accv[r] = bv;
        for (int k = 0; k < K; k++) {
            float wv = w_s[c * 133 + k];
            #pragma unroll
            for (int r = 0; r < 8; r++)
                accv[r] = fmaf(wv, e_s[(grp * 8 + r) * 129 + k], accv[r]);
        }
        #pragma unroll
        for (int r = 0; r < 8; r++) lg[(grp * 8 + r) * C + c] = accv[r];
    }
    __syncthreads();

    if (tid < CE_ROWS) {
        int   lab = g_lab[r0 + tid];
        float m = -1e30f;
        for (int cc = 0; cc < C; cc++) m = fmaxf(m, lg[tid * C + cc]);
        float s = 0.0f;
        for (int cc = 0; cc < C; cc++) s += expf(lg[tid * C + cc] - m);
        g_ce[r0 + tid] = m + logf(s) - lg[tid * C + lab];
    }
}

__global__ void __launch_bounds__(256, 1)
fused_kernel(const float* __restrict__ emb, const float* __restrict__ w,
             const float* __restrict__ bias) {
    extern __shared__ float sm[];
    if (blockIdx.x < PW_BLOCKS) pairwise_body(sm, emb, blockIdx.x);
    else                        ce_body(sm, emb, w, bias, blockIdx.x - PW_BLOCKS);
}

// ---------------------------------------------------------------------------
// Reductions: 32 blocks x 128 threads (one element/thread), then serial 32.
// ---------------------------------------------------------------------------
__global__ void reduce1_kernel() {
    __shared__ float s1[128], s2[128];
    int t = threadIdx.x;
    int i = blockIdx.x * 128 + t;
    float mx = fmaxf(__int_as_float(g_maxbits[i]), 1e-12f);
    float mn = fmaxf(__int_as_float(g_minbits[i]), 1e-12f);
    float tr = fmaxf(sqrtf(mx) - sqrtf(mn) + MARGIN, 0.0f);
    s1[t] = tr; s2[t] = g_ce[i];
    __syncthreads();
    #pragma unroll
    for (int s = 64; s > 0; s >>= 1) {
        if (t < s) { s1[t] += s1[t + s]; s2[t] += s2[t + s]; }
        __syncthreads();
    }
    if (t == 0) { g_part_tr[blockIdx.x] = s1[0]; g_part_ce[blockIdx.x] = s2[0]; }
}

__global__ void reduce2_kernel(float* __restrict__ out) {
    if (threadIdx.x == 0) {
        float s = 0.0f;
        #pragma unroll
        for (int i = 0; i < 32; i++) s += g_part_tr[i] + g_part_ce[i];
        out[0] = s * (1.0f / (float)B);
    }
}

// ---------------------------------------------------------------------------
extern "C" void kernel_launch(void* const* d_in, const int* in_sizes, int n_in,
                              void* d_out, int out_size) {
    const float* emb    = (const float*)d_in[0];
    const int*   labels = (const int*)d_in[1];
    const float* fcw    = (const float*)d_in[2];
    const float* fcb    = (const float*)d_in[3];
    float*       out    = (float*)d_out;

    cudaFuncSetAttribute(fused_kernel,
                         cudaFuncAttributeMaxDynamicSharedMemorySize, PW_SMEM);

    prep_kernel<<<(B * 32) / 256, 256>>>(emb, labels);
    fused_kernel<<<PW_BLOCKS + CE_BLOCKS, 256, PW_SMEM>>>(emb, fcw, fcb);
    reduce1_kernel<<<32, 128>>>();
    reduce2_kernel<<<1, 32>>>(out);
}